// round 1
// baseline (speedup 1.0000x reference)
#include <cuda_runtime.h>
#include <math.h>

// ---- problem dims (fixed) ----
#define B_    4
#define T_    20
#define N_    256
#define L_    (T_*N_)    // 5120
#define P_    (B_*L_)    // 20480
#define CMAP_ 2048
#define CC_   32
#define NPART 8
#define MPART 640        // 5120 / 8

typedef unsigned long long ull;

// ---- device scratch (no runtime allocation allowed) ----
__device__ float g_cm  [B_*256*CC_];      // compressed feature map, (b, h*16+w, 32)
__device__ float g_q   [P_*8];            // Q pre-scaled by -log2(e)
__device__ float g_kv  [P_*16];           // interleaved K[8] | V[8]
__device__ float g_part[NPART*(size_t)P_*8];

// ---- f32x2 packed-math helpers (ptxas never emits FFMA2 from C++) ----
__device__ __forceinline__ ull f2pack(float a, float b){ ull r; asm("mov.b64 %0,{%1,%2};":"=l"(r):"f"(a),"f"(b)); return r; }
__device__ __forceinline__ void f2unpack(ull v, float&a, float&b){ asm("mov.b64 {%0,%1},%2;":"=f"(a),"=f"(b):"l"(v)); }
__device__ __forceinline__ ull f2fma(ull a, ull b, ull c){ ull d; asm("fma.rn.f32x2 %0,%1,%2,%3;":"=l"(d):"l"(a),"l"(b),"l"(c)); return d; }
__device__ __forceinline__ ull f2mul(ull a, ull b){ ull d; asm("mul.rn.f32x2 %0,%1,%2;":"=l"(d):"l"(a),"l"(b)); return d; }
__device__ __forceinline__ float fex2(float x){ float r; asm("ex2.approx.f32 %0,%1;":"=f"(r):"f"(x)); return r; }
__device__ __forceinline__ float frcp(float x){ float r; asm("rcp.approx.f32 %0,%1;":"=f"(r):"f"(x)); return r; }
__device__ __forceinline__ float sigf(float x){ return 1.f/(1.f+expf(-x)); }  // precise, used only 20480x12 times

// ============================================================
// Kernel 1: compressor  cm[b,hw,o] = sum_c md[b,c,hw]*cw[o,c] + cb[o]
// grid: 32 blocks (b x 8 hw-tiles of 32), 256 threads (8 warps split c)
// ============================================================
__global__ void __launch_bounds__(256) k_compress(
    const float* __restrict__ md, const float* __restrict__ cw, const float* __restrict__ cb)
{
    __shared__ float wT[256][36];   // transposed comp_w chunk [c_local][o], padded to 144B rows (16B aligned)

    const int b    = blockIdx.x >> 3;
    const int tile = blockIdx.x & 7;
    const int tid  = threadIdx.x;
    const int lane = tid & 31;
    const int warp = tid >> 5;
    const int hw   = tile*32 + lane;

    ull acc[16];
    #pragma unroll
    for (int i=0;i<16;i++) acc[i] = 0ULL;

    for (int cb0 = 0; cb0 < CMAP_; cb0 += 256) {
        __syncthreads();
        // load comp_w chunk transposed: o = r, c_local = tid (coalesced gmem reads)
        #pragma unroll 4
        for (int r = 0; r < 32; r++)
            wT[tid][r] = cw[r*CMAP_ + cb0 + tid];
        __syncthreads();

        const int cl0 = warp*32;
        #pragma unroll 4
        for (int k = 0; k < 32; k++) {
            const int cl = cl0 + k;
            float m = md[(size_t)(b*CMAP_ + cb0 + cl)*256 + hw];  // coalesced across lanes
            ull m2 = f2pack(m, m);
            const ulonglong2* wrow = (const ulonglong2*)(&wT[cl][0]);
            #pragma unroll
            for (int i = 0; i < 8; i++) {
                ulonglong2 wv = wrow[i];
                acc[2*i]   = f2fma(m2, wv.x, acc[2*i]);
                acc[2*i+1] = f2fma(m2, wv.y, acc[2*i+1]);
            }
        }
    }

    // cross-warp (c-partition) reduction through smem
    __syncthreads();
    {
        ull* row = (ull*)&wT[tid][0];
        #pragma unroll
        for (int i = 0; i < 16; i++) row[i] = acc[i];
    }
    __syncthreads();

    const int hwl = tid & 31;
    const int og  = tid >> 5;       // 8 groups of 4 output channels
    float r0=0.f, r1=0.f, r2=0.f, r3=0.f;
    #pragma unroll
    for (int w2 = 0; w2 < 8; w2++) {
        const float* rr = &wT[w2*32 + hwl][og*4];
        r0 += rr[0]; r1 += rr[1]; r2 += rr[2]; r3 += rr[3];
    }
    const int hwg = tile*32 + hwl;
    float* o = &g_cm[(size_t)(b*256 + hwg)*CC_ + og*4];
    o[0] = r0 + cb[og*4+0];
    o[1] = r1 + cb[og*4+1];
    o[2] = r2 + cb[og*4+2];
    o[3] = r3 + cb[og*4+3];
}

// ============================================================
// Kernel 2: per-point preprocessing (PE + LSTM + grid-sample + vf + Q/K/V)
// 20480 threads, one point each
// ============================================================
__global__ void __launch_bounds__(256) k_points(
    const float* __restrict__ x,
    const float* __restrict__ w_ih, const float* __restrict__ b_ih, const float* __restrict__ b_hh,
    const float* __restrict__ vf_w, const float* __restrict__ vf_b,
    const float* __restrict__ fc_w, const float* __restrict__ fc_b,
    const float* __restrict__ fc2_w, const float* __restrict__ fc2_b,
    const float* __restrict__ fc3_w, const float* __restrict__ fc3_b)
{
    const int p = blockIdx.x*256 + threadIdx.x;
    const int b = p / L_;
    const int l = p % L_;
    const int t = l / N_;
    const int n = l % N_;

    const float x0 = x[((b*2+0)*T_ + t)*N_ + n];
    const float x1 = x[((b*2+1)*T_ + t)*N_ + n];
    const float ft = (float)t;
    const float xr0 = x0 + sinf(ft);
    const float xr1 = x1 + cosf(ft);

    // single-step LSTM (h0=c0=0): gate order i,f,g,o (f unused)
    float X[4];
    #pragma unroll
    for (int j = 0; j < 4; j++) {
        float ig = fmaf(w_ih[2*j],        xr0, fmaf(w_ih[2*j+1],        xr1, b_ih[j]    + b_hh[j]));
        float gg = fmaf(w_ih[2*(8+j)],    xr0, fmaf(w_ih[2*(8+j)+1],    xr1, b_ih[8+j]  + b_hh[8+j]));
        float og = fmaf(w_ih[2*(12+j)],   xr0, fmaf(w_ih[2*(12+j)+1],   xr1, b_ih[12+j] + b_hh[12+j]));
        float c  = sigf(ig)*tanhf(gg);
        X[j] = sigf(og)*tanhf(c);
    }

    // bilinear grid-sample of cm (align_corners=False, zero padding)
    // ix = x0/32 - 0.5, iy = x1/32 - 0.5
    const float ix = x0*(1.f/32.f) - 0.5f;
    const float iy = x1*(1.f/32.f) - 0.5f;
    const float x0f = floorf(ix), y0f = floorf(iy);
    const float wx1 = ix - x0f, wx0 = 1.f - wx1;
    const float wy1 = iy - y0f, wy0 = 1.f - wy1;
    const int xi0 = (int)x0f, yi0 = (int)y0f;

    float lc[32];
    #pragma unroll
    for (int i = 0; i < 32; i++) lc[i] = 0.f;

    #pragma unroll
    for (int cy = 0; cy < 2; cy++) {
        #pragma unroll
        for (int cx = 0; cx < 2; cx++) {
            const int xi = xi0 + cx, yi = yi0 + cy;
            const float wgt = (cx ? wx1 : wx0) * (cy ? wy1 : wy0);
            if (xi >= 0 && xi < 16 && yi >= 0 && yi < 16) {
                const float4* src = (const float4*)&g_cm[(size_t)(b*256 + yi*16 + xi)*CC_];
                #pragma unroll
                for (int i = 0; i < 8; i++) {
                    float4 v = src[i];
                    lc[4*i+0] = fmaf(wgt, v.x, lc[4*i+0]);
                    lc[4*i+1] = fmaf(wgt, v.y, lc[4*i+1]);
                    lc[4*i+2] = fmaf(wgt, v.z, lc[4*i+2]);
                    lc[4*i+3] = fmaf(wgt, v.w, lc[4*i+3]);
                }
            }
        }
    }

    // vf: fused = [X(4), lc(32)] -> X2(4)
    float X2[4];
    #pragma unroll
    for (int i = 0; i < 4; i++) {
        float s = vf_b[i];
        #pragma unroll
        for (int j = 0; j < 4; j++)  s = fmaf(vf_w[i*36+j],   X[j],  s);
        #pragma unroll
        for (int j = 0; j < 32; j++) s = fmaf(vf_w[i*36+4+j], lc[j], s);
        X2[i] = s;
    }

    // Q (scaled by -log2e so attention can use ex2 directly), K, V
    const float NEGL2E = -1.4426950408889634f;
    #pragma unroll
    for (int k = 0; k < 8; k++) {
        float q = fc_b[k];
        #pragma unroll
        for (int i = 0; i < 4; i++) q = fmaf(fc_w[k*4+i], X2[i], q);
        g_q[(size_t)p*8 + k] = q * NEGL2E;
        g_kv[(size_t)p*16 + k]     = fmaf(fc2_w[2*k], xr0, fmaf(fc2_w[2*k+1], xr1, fc2_b[k]));
        g_kv[(size_t)p*16 + 8 + k] = fmaf(fc3_w[2*k], xr0, fmaf(fc3_w[2*k+1], xr1, fc3_b[k]));
    }
}

// ============================================================
// Kernel 3: attention partials
// grid (20 l-tiles, 8 m-parts, 4 batches) = 640 blocks, 256 threads
// each thread: one l, 640 m's; inner loop = 4 LDS.128 + 8 FFMA2 + EX2 + RCP
// ============================================================
__global__ void __launch_bounds__(256) k_attn()
{
    __shared__ float skv[MPART*16];   // 40 KB

    const int b  = blockIdx.z;
    const int mp = blockIdx.y;
    const int l  = blockIdx.x*256 + threadIdx.x;

    // cooperative KV tile load (coalesced float4)
    {
        const float4* src = (const float4*)(g_kv + ((size_t)b*L_ + (size_t)mp*MPART)*16);
        float4* dst = (float4*)skv;
        #pragma unroll
        for (int i = threadIdx.x; i < MPART*4; i += 256) dst[i] = src[i];
    }

    ull q0,q1,q2,q3;
    {
        const float4* qp = (const float4*)(g_q + ((size_t)b*L_ + l)*8);
        float4 qa = qp[0], qb = qp[1];
        q0 = f2pack(qa.x, qa.y); q1 = f2pack(qa.z, qa.w);
        q2 = f2pack(qb.x, qb.y); q3 = f2pack(qb.z, qb.w);
    }
    __syncthreads();

    ull acc0 = 0ULL, acc1 = 0ULL, acc2 = 0ULL, acc3 = 0ULL;
    const ulonglong2* kvp = (const ulonglong2*)skv;

    #pragma unroll 4
    for (int m = 0; m < MPART; m++) {
        ulonglong2 kA = kvp[m*4+0];
        ulonglong2 kB = kvp[m*4+1];
        ulonglong2 vA = kvp[m*4+2];
        ulonglong2 vB = kvp[m*4+3];
        // arg = -(Q.K)*log2e  (scale folded into Q)
        ull d = f2fma(q0, kA.x, f2fma(q1, kA.y, f2fma(q2, kB.x, f2mul(q3, kB.y))));
        float lo, hi; f2unpack(d, lo, hi);
        float s = frcp(1.f + fex2(lo + hi));   // sigmoid(Q.K)
        ull s2 = f2pack(s, s);
        acc0 = f2fma(s2, vA.x, acc0);
        acc1 = f2fma(s2, vA.y, acc1);
        acc2 = f2fma(s2, vB.x, acc2);
        acc3 = f2fma(s2, vB.y, acc3);
    }

    ull* op = (ull*)(g_part + ((size_t)mp*P_ + (size_t)b*L_ + l)*8);
    ulonglong2 w0; w0.x = acc0; w0.y = acc1;
    ulonglong2 w1; w1.x = acc2; w1.y = acc3;
    ((ulonglong2*)op)[0] = w0;
    ((ulonglong2*)op)[1] = w1;
}

// ============================================================
// Kernel 4: combine partials + threshold_relu + fco -> d_out (b,2,t,n)
// ============================================================
__global__ void __launch_bounds__(256) k_combine(
    const float* __restrict__ fco_w, const float* __restrict__ fco_b, float* __restrict__ out)
{
    const int p = blockIdx.x*256 + threadIdx.x;

    float o[8];
    #pragma unroll
    for (int j = 0; j < 8; j++) o[j] = 0.f;

    #pragma unroll
    for (int s = 0; s < NPART; s++) {
        const float4* pp = (const float4*)(g_part + ((size_t)s*P_ + p)*8);
        float4 a = pp[0], c = pp[1];
        o[0]+=a.x; o[1]+=a.y; o[2]+=a.z; o[3]+=a.w;
        o[4]+=c.x; o[5]+=c.y; o[6]+=c.z; o[7]+=c.w;
    }
    #pragma unroll
    for (int j = 0; j < 8; j++) o[j] = (o[j] > 0.5f) ? o[j] : 0.f;

    float r0 = fco_b[0], r1 = fco_b[1];
    #pragma unroll
    for (int j = 0; j < 8; j++) {
        r0 = fmaf(fco_w[j],   o[j], r0);
        r1 = fmaf(fco_w[8+j], o[j], r1);
    }

    const int b = p / L_;
    const int l = p % L_;
    const int t = l / N_;
    const int n = l % N_;
    out[((b*2+0)*T_ + t)*N_ + n] = r0;
    out[((b*2+1)*T_ + t)*N_ + n] = r1;
}

// ============================================================
extern "C" void kernel_launch(void* const* d_in, const int* in_sizes, int n_in,
                              void* d_out, int out_size)
{
    const float* x      = (const float*)d_in[0];
    const float* md     = (const float*)d_in[1];
    const float* w_ih   = (const float*)d_in[2];
    const float* b_ih   = (const float*)d_in[3];
    const float* b_hh   = (const float*)d_in[4];
    const float* comp_w = (const float*)d_in[5];
    const float* comp_b = (const float*)d_in[6];
    const float* vf_w   = (const float*)d_in[7];
    const float* vf_b   = (const float*)d_in[8];
    const float* fc_w   = (const float*)d_in[9];
    const float* fc_b   = (const float*)d_in[10];
    const float* fc2_w  = (const float*)d_in[11];
    const float* fc2_b  = (const float*)d_in[12];
    const float* fc3_w  = (const float*)d_in[13];
    const float* fc3_b  = (const float*)d_in[14];
    const float* fco_w  = (const float*)d_in[15];
    const float* fco_b  = (const float*)d_in[16];
    float* out = (float*)d_out;

    k_compress<<<32, 256>>>(md, comp_w, comp_b);
    k_points<<<P_/256, 256>>>(x, w_ih, b_ih, b_hh, vf_w, vf_b,
                              fc_w, fc_b, fc2_w, fc2_b, fc3_w, fc3_b);
    k_attn<<<dim3(L_/256, NPART, B_), 256>>>();
    k_combine<<<P_/256, 256>>>(fco_w, fco_b, out);
}

// round 2
// speedup vs baseline: 1.3933x; 1.3933x over previous
#include <cuda_runtime.h>
#include <math.h>

// ---- problem dims (fixed) ----
#define B_    4
#define T_    20
#define N_    256
#define L_    (T_*N_)    // 5120
#define P_    (B_*L_)    // 20480
#define CMAP_ 2048
#define CC_   32
#define NPART 32
#define MPART 160        // 5120 / 32

typedef unsigned long long ull;

// ---- device scratch (no runtime allocation allowed) ----
__device__ float g_cm4 [4*B_*256*4];      // per-c-part vf-projected feature map (part,b,hw,4)
__device__ float g_q   [P_*8];            // Q pre-scaled by -log2(e)
__device__ float g_kv  [P_*16];           // interleaved K[8] | V[8]
__device__ float g_part[NPART*(size_t)P_*8];

// ---- f32x2 packed-math helpers ----
__device__ __forceinline__ ull f2pack(float a, float b){ ull r; asm("mov.b64 %0,{%1,%2};":"=l"(r):"f"(a),"f"(b)); return r; }
__device__ __forceinline__ void f2unpack(ull v, float&a, float&b){ asm("mov.b64 {%0,%1},%2;":"=f"(a),"=f"(b):"l"(v)); }
__device__ __forceinline__ ull f2fma(ull a, ull b, ull c){ ull d; asm("fma.rn.f32x2 %0,%1,%2,%3;":"=l"(d):"l"(a),"l"(b),"l"(c)); return d; }
__device__ __forceinline__ ull f2mul(ull a, ull b){ ull d; asm("mul.rn.f32x2 %0,%1,%2;":"=l"(d):"l"(a),"l"(b)); return d; }
__device__ __forceinline__ float fex2(float x){ float r; asm("ex2.approx.f32 %0,%1;":"=f"(r):"f"(x)); return r; }
__device__ __forceinline__ float frcp(float x){ float r; asm("rcp.approx.f32 %0,%1;":"=f"(r):"f"(x)); return r; }
__device__ __forceinline__ float sigf(float x){ return 1.f/(1.f+expf(-x)); }  // precise path (k_points only)

// ============================================================
// Kernel 1: compressor + folded vf projection
// cm[b,hw,o] = sum_c md[b,c,hw]*cw[o,c] (+cb[o] in part 0)
// proj[part,b,hw,i] = sum_o vf_w[i][4+o] * cm[b,hw,o]
// grid: 128 blocks = b(4) x hw-tile(8) x c-part(4), 256 threads
// ============================================================
__global__ void __launch_bounds__(256) k_compress(
    const float* __restrict__ md, const float* __restrict__ cw, const float* __restrict__ cb,
    const float* __restrict__ vf_w)
{
    __shared__ float wT[256][36];    // transposed comp_w chunk [c_local][o]
    __shared__ float cm32[32][33];   // reduced 32-channel cm for this hw tile

    const int cpart = blockIdx.x & 3;
    const int tile  = (blockIdx.x >> 2) & 7;
    const int b     = blockIdx.x >> 5;
    const int tid  = threadIdx.x;
    const int lane = tid & 31;
    const int warp = tid >> 5;
    const int hw   = tile*32 + lane;

    ull acc[16];
    #pragma unroll
    for (int i=0;i<16;i++) acc[i] = 0ULL;

    #pragma unroll
    for (int chunk = 0; chunk < 2; chunk++) {
        const int cb0 = cpart*512 + chunk*256;
        __syncthreads();
        #pragma unroll 4
        for (int r = 0; r < 32; r++)
            wT[tid][r] = cw[r*CMAP_ + cb0 + tid];
        __syncthreads();

        const int cl0 = warp*32;
        #pragma unroll 4
        for (int k = 0; k < 32; k++) {
            const int cl = cl0 + k;
            float m = md[(size_t)(b*CMAP_ + cb0 + cl)*256 + hw];
            ull m2 = f2pack(m, m);
            const ulonglong2* wrow = (const ulonglong2*)(&wT[cl][0]);
            #pragma unroll
            for (int i = 0; i < 8; i++) {
                ulonglong2 wv = wrow[i];
                acc[2*i]   = f2fma(m2, wv.x, acc[2*i]);
                acc[2*i+1] = f2fma(m2, wv.y, acc[2*i+1]);
            }
        }
    }

    // dump per-warp partials to smem
    __syncthreads();
    {
        ull* row = (ull*)&wT[tid][0];
        #pragma unroll
        for (int i = 0; i < 16; i++) row[i] = acc[i];
    }
    __syncthreads();

    // cross-warp reduce: thread (hwl, og) sums channel group og*4..og*4+3
    const int hwl = tid & 31;
    const int og  = tid >> 5;
    float r0=0.f, r1=0.f, r2=0.f, r3=0.f;
    #pragma unroll
    for (int w2 = 0; w2 < 8; w2++) {
        const float* rr = &wT[w2*32 + hwl][og*4];
        r0 += rr[0]; r1 += rr[1]; r2 += rr[2]; r3 += rr[3];
    }
    if (cpart == 0) {   // comp_b counted exactly once across parts
        r0 += cb[og*4+0]; r1 += cb[og*4+1]; r2 += cb[og*4+2]; r3 += cb[og*4+3];
    }
    cm32[hwl][og*4+0] = r0; cm32[hwl][og*4+1] = r1;
    cm32[hwl][og*4+2] = r2; cm32[hwl][og*4+3] = r3;
    __syncthreads();

    // fold vf projection: 32 channels -> 4 (bilinear sampling commutes with it)
    if (og < 4) {
        float s = 0.f;
        #pragma unroll
        for (int j = 0; j < 32; j++)
            s = fmaf(vf_w[og*36 + 4 + j], cm32[hwl][j], s);
        g_cm4[(((size_t)cpart*B_ + b)*256 + tile*32 + hwl)*4 + og] = s;
    }
}

// ============================================================
// Kernel 2: per-point preprocessing (PE + LSTM + sample proj + Q/K/V)
// ============================================================
__global__ void __launch_bounds__(256) k_points(
    const float* __restrict__ x,
    const float* __restrict__ w_ih, const float* __restrict__ b_ih, const float* __restrict__ b_hh,
    const float* __restrict__ vf_w, const float* __restrict__ vf_b,
    const float* __restrict__ fc_w, const float* __restrict__ fc_b,
    const float* __restrict__ fc2_w, const float* __restrict__ fc2_b,
    const float* __restrict__ fc3_w, const float* __restrict__ fc3_b)
{
    const int p = blockIdx.x*256 + threadIdx.x;
    const int b = p / L_;
    const int l = p % L_;
    const int t = l / N_;
    const int n = l % N_;

    const float x0 = x[((b*2+0)*T_ + t)*N_ + n];
    const float x1 = x[((b*2+1)*T_ + t)*N_ + n];
    const float ft = (float)t;
    const float xr0 = x0 + sinf(ft);
    const float xr1 = x1 + cosf(ft);

    // single-step LSTM (h0=c0=0): gate order i,f,g,o (f unused)
    float X[4];
    #pragma unroll
    for (int j = 0; j < 4; j++) {
        float ig = fmaf(w_ih[2*j],      xr0, fmaf(w_ih[2*j+1],      xr1, b_ih[j]    + b_hh[j]));
        float gg = fmaf(w_ih[2*(8+j)],  xr0, fmaf(w_ih[2*(8+j)+1],  xr1, b_ih[8+j]  + b_hh[8+j]));
        float og = fmaf(w_ih[2*(12+j)], xr0, fmaf(w_ih[2*(12+j)+1], xr1, b_ih[12+j] + b_hh[12+j]));
        float c  = sigf(ig)*tanhf(gg);
        X[j] = sigf(og)*tanhf(c);
    }

    // bilinear sample of the projected map (align_corners=False, zero pad)
    const float ix = x0*(1.f/32.f) - 0.5f;
    const float iy = x1*(1.f/32.f) - 0.5f;
    const float x0f = floorf(ix), y0f = floorf(iy);
    const float wx1 = ix - x0f, wx0 = 1.f - wx1;
    const float wy1 = iy - y0f, wy0 = 1.f - wy1;
    const int xi0 = (int)x0f, yi0 = (int)y0f;

    float lcp0=0.f, lcp1=0.f, lcp2=0.f, lcp3=0.f;
    #pragma unroll
    for (int cy = 0; cy < 2; cy++) {
        #pragma unroll
        for (int cx = 0; cx < 2; cx++) {
            const int xi = xi0 + cx, yi = yi0 + cy;
            const float wgt = (cx ? wx1 : wx0) * (cy ? wy1 : wy0);
            if (xi >= 0 && xi < 16 && yi >= 0 && yi < 16) {
                #pragma unroll
                for (int part = 0; part < 4; part++) {
                    float4 v = *(const float4*)&g_cm4[(((size_t)part*B_ + b)*256 + yi*16 + xi)*4];
                    lcp0 = fmaf(wgt, v.x, lcp0);
                    lcp1 = fmaf(wgt, v.y, lcp1);
                    lcp2 = fmaf(wgt, v.z, lcp2);
                    lcp3 = fmaf(wgt, v.w, lcp3);
                }
            }
        }
    }

    // X2 = vf_b + vf_w[:, :4] @ X + sampled projection
    float X2[4];
    {
        float lcp[4] = {lcp0, lcp1, lcp2, lcp3};
        #pragma unroll
        for (int i = 0; i < 4; i++) {
            float s = vf_b[i] + lcp[i];
            #pragma unroll
            for (int j = 0; j < 4; j++) s = fmaf(vf_w[i*36+j], X[j], s);
            X2[i] = s;
        }
    }

    // Q (scaled by -log2e for ex2-based sigmoid), K, V
    const float NEGL2E = -1.4426950408889634f;
    #pragma unroll
    for (int k = 0; k < 8; k++) {
        float q = fc_b[k];
        #pragma unroll
        for (int i = 0; i < 4; i++) q = fmaf(fc_w[k*4+i], X2[i], q);
        g_q[(size_t)p*8 + k] = q * NEGL2E;
        g_kv[(size_t)p*16 + k]     = fmaf(fc2_w[2*k], xr0, fmaf(fc2_w[2*k+1], xr1, fc2_b[k]));
        g_kv[(size_t)p*16 + 8 + k] = fmaf(fc3_w[2*k], xr0, fmaf(fc3_w[2*k+1], xr1, fc3_b[k]));
    }
}

// ============================================================
// Kernel 3: attention partials — 2 queries per thread
// grid (10 l-tiles, 32 m-parts, 4 batches) = 1280 blocks, 256 threads
// ============================================================
__global__ void __launch_bounds__(256, 3) k_attn()
{
    __shared__ float skv[MPART*16];   // 10 KB

    const int b  = blockIdx.z;
    const int mp = blockIdx.y;
    const int l0 = blockIdx.x*512 + threadIdx.x;   // query 0
    const int l1 = l0 + 256;                        // query 1

    // cooperative KV tile load (coalesced float4): 640 float4
    {
        const float4* src = (const float4*)(g_kv + ((size_t)b*L_ + (size_t)mp*MPART)*16);
        float4* dst = (float4*)skv;
        #pragma unroll
        for (int i = threadIdx.x; i < MPART*4; i += 256) dst[i] = src[i];
    }

    ull q0,q1,q2,q3, q4,q5,q6,q7;
    {
        const float4* qp = (const float4*)(g_q + ((size_t)b*L_ + l0)*8);
        float4 qa = qp[0], qb = qp[1];
        q0 = f2pack(qa.x, qa.y); q1 = f2pack(qa.z, qa.w);
        q2 = f2pack(qb.x, qb.y); q3 = f2pack(qb.z, qb.w);
        const float4* qq = (const float4*)(g_q + ((size_t)b*L_ + l1)*8);
        float4 qc = qq[0], qd = qq[1];
        q4 = f2pack(qc.x, qc.y); q5 = f2pack(qc.z, qc.w);
        q6 = f2pack(qd.x, qd.y); q7 = f2pack(qd.z, qd.w);
    }
    __syncthreads();

    ull a0=0ULL,a1=0ULL,a2=0ULL,a3=0ULL, a4=0ULL,a5=0ULL,a6=0ULL,a7=0ULL;
    const ulonglong2* kvp = (const ulonglong2*)skv;

    #pragma unroll 2
    for (int m = 0; m < MPART; m++) {
        ulonglong2 kA = kvp[m*4+0];
        ulonglong2 kB = kvp[m*4+1];
        ulonglong2 vA = kvp[m*4+2];
        ulonglong2 vB = kvp[m*4+3];
        // scaled scores (scale -log2e folded into Q)
        ull d0 = f2fma(q0, kA.x, f2fma(q1, kA.y, f2fma(q2, kB.x, f2mul(q3, kB.y))));
        ull d1 = f2fma(q4, kA.x, f2fma(q5, kA.y, f2fma(q6, kB.x, f2mul(q7, kB.y))));
        float e0lo, e0hi; f2unpack(d0, e0lo, e0hi);
        float e1lo, e1hi; f2unpack(d1, e1lo, e1hi);
        float s0 = frcp(1.f + fex2(e0lo + e0hi));
        float s1 = frcp(1.f + fex2(e1lo + e1hi));
        ull s00 = f2pack(s0, s0);
        ull s11 = f2pack(s1, s1);
        a0 = f2fma(s00, vA.x, a0); a1 = f2fma(s00, vA.y, a1);
        a2 = f2fma(s00, vB.x, a2); a3 = f2fma(s00, vB.y, a3);
        a4 = f2fma(s11, vA.x, a4); a5 = f2fma(s11, vA.y, a5);
        a6 = f2fma(s11, vB.x, a6); a7 = f2fma(s11, vB.y, a7);
    }

    {
        ulonglong2 w0; w0.x = a0; w0.y = a1;
        ulonglong2 w1; w1.x = a2; w1.y = a3;
        ulonglong2* op0 = (ulonglong2*)(g_part + ((size_t)mp*P_ + (size_t)b*L_ + l0)*8);
        op0[0] = w0; op0[1] = w1;
        ulonglong2 w2; w2.x = a4; w2.y = a5;
        ulonglong2 w3; w3.x = a6; w3.y = a7;
        ulonglong2* op1 = (ulonglong2*)(g_part + ((size_t)mp*P_ + (size_t)b*L_ + l1)*8);
        op1[0] = w2; op1[1] = w3;
    }
}

// ============================================================
// Kernel 4: combine 32 partials + threshold_relu + fco -> out (b,2,t,n)
// 2 threads per point (float4 halves), pairwise shfl for the 8-dot
// ============================================================
__global__ void __launch_bounds__(256) k_combine(
    const float* __restrict__ fco_w, const float* __restrict__ fco_b, float* __restrict__ out)
{
    const int idx = blockIdx.x*256 + threadIdx.x;
    const int p = idx >> 1;
    const int h = idx & 1;      // half: 0 -> comps 0..3, 1 -> comps 4..7

    float o0=0.f, o1=0.f, o2=0.f, o3=0.f;
    #pragma unroll
    for (int s = 0; s < NPART; s++) {
        float4 a = *(const float4*)(g_part + (((size_t)s*P_ + p)*8) + h*4);
        o0 += a.x; o1 += a.y; o2 += a.z; o3 += a.w;
    }
    o0 = (o0 > 0.5f) ? o0 : 0.f;
    o1 = (o1 > 0.5f) ? o1 : 0.f;
    o2 = (o2 > 0.5f) ? o2 : 0.f;
    o3 = (o3 > 0.5f) ? o3 : 0.f;

    const float* w0 = fco_w + h*4;        // row 0 slice
    const float* w1 = fco_w + 8 + h*4;    // row 1 slice
    float c0 = w0[0]*o0 + w0[1]*o1 + w0[2]*o2 + w0[3]*o3;
    float c1 = w1[0]*o0 + w1[1]*o1 + w1[2]*o2 + w1[3]*o3;
    c0 += __shfl_xor_sync(0xffffffffu, c0, 1);
    c1 += __shfl_xor_sync(0xffffffffu, c1, 1);

    const int b = p / L_;
    const int l = p % L_;
    const int t = l / N_;
    const int n = l % N_;
    if (h == 0) out[((b*2+0)*T_ + t)*N_ + n] = c0 + fco_b[0];
    else        out[((b*2+1)*T_ + t)*N_ + n] = c1 + fco_b[1];
}

// ============================================================
extern "C" void kernel_launch(void* const* d_in, const int* in_sizes, int n_in,
                              void* d_out, int out_size)
{
    const float* x      = (const float*)d_in[0];
    const float* md     = (const float*)d_in[1];
    const float* w_ih   = (const float*)d_in[2];
    const float* b_ih   = (const float*)d_in[3];
    const float* b_hh   = (const float*)d_in[4];
    const float* comp_w = (const float*)d_in[5];
    const float* comp_b = (const float*)d_in[6];
    const float* vf_w   = (const float*)d_in[7];
    const float* vf_b   = (const float*)d_in[8];
    const float* fc_w   = (const float*)d_in[9];
    const float* fc_b   = (const float*)d_in[10];
    const float* fc2_w  = (const float*)d_in[11];
    const float* fc2_b  = (const float*)d_in[12];
    const float* fc3_w  = (const float*)d_in[13];
    const float* fc3_b  = (const float*)d_in[14];
    const float* fco_w  = (const float*)d_in[15];
    const float* fco_b  = (const float*)d_in[16];
    float* out = (float*)d_out;

    k_compress<<<128, 256>>>(md, comp_w, comp_b, vf_w);
    k_points<<<P_/256, 256>>>(x, w_ih, b_ih, b_hh, vf_w, vf_b,
                              fc_w, fc_b, fc2_w, fc2_b, fc3_w, fc3_b);
    k_attn<<<dim3(L_/512, NPART, B_), 256>>>();
    k_combine<<<(P_*2)/256, 256>>>(fco_w, fco_b, out);
}

// round 3
// speedup vs baseline: 1.4040x; 1.0077x over previous
#include <cuda_runtime.h>
#include <math.h>

// ---- problem dims (fixed) ----
#define B_    4
#define T_    20
#define N_    256
#define L_    (T_*N_)    // 5120
#define P_    (B_*L_)    // 20480
#define CMAP_ 2048
#define CC_   32
#define NPART 40
#define MPART 128        // 5120 / 40

typedef unsigned long long ull;

// ---- device scratch (no runtime allocation allowed) ----
__device__ float g_cm4 [4*B_*256*4];      // per-c-part vf-projected feature map (part,b,hw,4)
__device__ float g_q   [P_*8];            // Q pre-scaled by -log2(e)
__device__ float g_kv  [P_*16];           // interleaved K[8] | V[8]
__device__ float g_part[NPART*(size_t)P_*8];

// ---- f32x2 packed-math helpers ----
__device__ __forceinline__ ull f2pack(float a, float b){ ull r; asm("mov.b64 %0,{%1,%2};":"=l"(r):"f"(a),"f"(b)); return r; }
__device__ __forceinline__ void f2unpack(ull v, float&a, float&b){ asm("mov.b64 {%0,%1},%2;":"=f"(a),"=f"(b):"l"(v)); }
__device__ __forceinline__ ull f2fma(ull a, ull b, ull c){ ull d; asm("fma.rn.f32x2 %0,%1,%2,%3;":"=l"(d):"l"(a),"l"(b),"l"(c)); return d; }
__device__ __forceinline__ ull f2mul(ull a, ull b){ ull d; asm("mul.rn.f32x2 %0,%1,%2;":"=l"(d):"l"(a),"l"(b)); return d; }
__device__ __forceinline__ float fex2(float x){ float r; asm("ex2.approx.f32 %0,%1;":"=f"(r):"f"(x)); return r; }
__device__ __forceinline__ float frcp(float x){ float r; asm("rcp.approx.f32 %0,%1;":"=f"(r):"f"(x)); return r; }
__device__ __forceinline__ float sigf(float x){ return 1.f/(1.f+expf(-x)); }  // precise path (k_points only)

// ============================================================
// Kernel 1: compressor + folded vf projection
// grid: 128 blocks = b(4) x hw-tile(8) x c-part(4), 256 threads
// ============================================================
__global__ void __launch_bounds__(256) k_compress(
    const float* __restrict__ md, const float* __restrict__ cw, const float* __restrict__ cb,
    const float* __restrict__ vf_w)
{
    __shared__ float wT[256][36];    // transposed comp_w chunk [c_local][o]
    __shared__ float cm32[32][33];   // reduced 32-channel cm for this hw tile

    const int cpart = blockIdx.x & 3;
    const int tile  = (blockIdx.x >> 2) & 7;
    const int b     = blockIdx.x >> 5;
    const int tid  = threadIdx.x;
    const int lane = tid & 31;
    const int warp = tid >> 5;
    const int hw   = tile*32 + lane;

    ull acc[16];
    #pragma unroll
    for (int i=0;i<16;i++) acc[i] = 0ULL;

    #pragma unroll
    for (int chunk = 0; chunk < 2; chunk++) {
        const int cb0 = cpart*512 + chunk*256;
        __syncthreads();
        #pragma unroll 4
        for (int r = 0; r < 32; r++)
            wT[tid][r] = cw[r*CMAP_ + cb0 + tid];
        __syncthreads();

        const int cl0 = warp*32;
        #pragma unroll 4
        for (int k = 0; k < 32; k++) {
            const int cl = cl0 + k;
            float m = md[(size_t)(b*CMAP_ + cb0 + cl)*256 + hw];
            ull m2 = f2pack(m, m);
            const ulonglong2* wrow = (const ulonglong2*)(&wT[cl][0]);
            #pragma unroll
            for (int i = 0; i < 8; i++) {
                ulonglong2 wv = wrow[i];
                acc[2*i]   = f2fma(m2, wv.x, acc[2*i]);
                acc[2*i+1] = f2fma(m2, wv.y, acc[2*i+1]);
            }
        }
    }

    __syncthreads();
    {
        ull* row = (ull*)&wT[tid][0];
        #pragma unroll
        for (int i = 0; i < 16; i++) row[i] = acc[i];
    }
    __syncthreads();

    const int hwl = tid & 31;
    const int og  = tid >> 5;
    float r0=0.f, r1=0.f, r2=0.f, r3=0.f;
    #pragma unroll
    for (int w2 = 0; w2 < 8; w2++) {
        const float* rr = &wT[w2*32 + hwl][og*4];
        r0 += rr[0]; r1 += rr[1]; r2 += rr[2]; r3 += rr[3];
    }
    if (cpart == 0) {
        r0 += cb[og*4+0]; r1 += cb[og*4+1]; r2 += cb[og*4+2]; r3 += cb[og*4+3];
    }
    cm32[hwl][og*4+0] = r0; cm32[hwl][og*4+1] = r1;
    cm32[hwl][og*4+2] = r2; cm32[hwl][og*4+3] = r3;
    __syncthreads();

    if (og < 4) {
        float s = 0.f;
        #pragma unroll
        for (int j = 0; j < 32; j++)
            s = fmaf(vf_w[og*36 + 4 + j], cm32[hwl][j], s);
        g_cm4[(((size_t)cpart*B_ + b)*256 + tile*32 + hwl)*4 + og] = s;
    }
}

// ============================================================
// Kernel 2: per-point preprocessing (PE + LSTM + sample proj + Q/K/V)
// ============================================================
__global__ void __launch_bounds__(256) k_points(
    const float* __restrict__ x,
    const float* __restrict__ w_ih, const float* __restrict__ b_ih, const float* __restrict__ b_hh,
    const float* __restrict__ vf_w, const float* __restrict__ vf_b,
    const float* __restrict__ fc_w, const float* __restrict__ fc_b,
    const float* __restrict__ fc2_w, const float* __restrict__ fc2_b,
    const float* __restrict__ fc3_w, const float* __restrict__ fc3_b)
{
    const int p = blockIdx.x*256 + threadIdx.x;
    const int b = p / L_;
    const int l = p % L_;
    const int t = l / N_;
    const int n = l % N_;

    const float x0 = x[((b*2+0)*T_ + t)*N_ + n];
    const float x1 = x[((b*2+1)*T_ + t)*N_ + n];
    const float ft = (float)t;
    const float xr0 = x0 + sinf(ft);
    const float xr1 = x1 + cosf(ft);

    float X[4];
    #pragma unroll
    for (int j = 0; j < 4; j++) {
        float ig = fmaf(w_ih[2*j],      xr0, fmaf(w_ih[2*j+1],      xr1, b_ih[j]    + b_hh[j]));
        float gg = fmaf(w_ih[2*(8+j)],  xr0, fmaf(w_ih[2*(8+j)+1],  xr1, b_ih[8+j]  + b_hh[8+j]));
        float og = fmaf(w_ih[2*(12+j)], xr0, fmaf(w_ih[2*(12+j)+1], xr1, b_ih[12+j] + b_hh[12+j]));
        float c  = sigf(ig)*tanhf(gg);
        X[j] = sigf(og)*tanhf(c);
    }

    const float ix = x0*(1.f/32.f) - 0.5f;
    const float iy = x1*(1.f/32.f) - 0.5f;
    const float x0f = floorf(ix), y0f = floorf(iy);
    const float wx1 = ix - x0f, wx0 = 1.f - wx1;
    const float wy1 = iy - y0f, wy0 = 1.f - wy1;
    const int xi0 = (int)x0f, yi0 = (int)y0f;

    float lcp0=0.f, lcp1=0.f, lcp2=0.f, lcp3=0.f;
    #pragma unroll
    for (int cy = 0; cy < 2; cy++) {
        #pragma unroll
        for (int cx = 0; cx < 2; cx++) {
            const int xi = xi0 + cx, yi = yi0 + cy;
            const float wgt = (cx ? wx1 : wx0) * (cy ? wy1 : wy0);
            if (xi >= 0 && xi < 16 && yi >= 0 && yi < 16) {
                #pragma unroll
                for (int part = 0; part < 4; part++) {
                    float4 v = *(const float4*)&g_cm4[(((size_t)part*B_ + b)*256 + yi*16 + xi)*4];
                    lcp0 = fmaf(wgt, v.x, lcp0);
                    lcp1 = fmaf(wgt, v.y, lcp1);
                    lcp2 = fmaf(wgt, v.z, lcp2);
                    lcp3 = fmaf(wgt, v.w, lcp3);
                }
            }
        }
    }

    float X2[4];
    {
        float lcp[4] = {lcp0, lcp1, lcp2, lcp3};
        #pragma unroll
        for (int i = 0; i < 4; i++) {
            float s = vf_b[i] + lcp[i];
            #pragma unroll
            for (int j = 0; j < 4; j++) s = fmaf(vf_w[i*36+j], X[j], s);
            X2[i] = s;
        }
    }

    const float NEGL2E = -1.4426950408889634f;
    #pragma unroll
    for (int k = 0; k < 8; k++) {
        float q = fc_b[k];
        #pragma unroll
        for (int i = 0; i < 4; i++) q = fmaf(fc_w[k*4+i], X2[i], q);
        g_q[(size_t)p*8 + k] = q * NEGL2E;
        g_kv[(size_t)p*16 + k]     = fmaf(fc2_w[2*k], xr0, fmaf(fc2_w[2*k+1], xr1, fc2_b[k]));
        g_kv[(size_t)p*16 + 8 + k] = fmaf(fc3_w[2*k], xr0, fmaf(fc3_w[2*k+1], xr1, fc3_b[k]));
    }
}

// ============================================================
// Kernel 3: attention partials — 4 queries per thread
// grid (5 l-tiles, 40 m-parts, 4 batches) = 800 blocks, 256 threads
// ============================================================
__global__ void __launch_bounds__(256, 2) k_attn()
{
    __shared__ float skv[MPART*16];   // 8 KB

    const int b  = blockIdx.z;
    const int mp = blockIdx.y;
    const int lb = blockIdx.x*1024 + threadIdx.x;   // query 0 of 4 (stride 256)

    // cooperative KV tile load (coalesced float4): 512 float4
    {
        const float4* src = (const float4*)(g_kv + ((size_t)b*L_ + (size_t)mp*MPART)*16);
        float4* dst = (float4*)skv;
        #pragma unroll
        for (int i = threadIdx.x; i < MPART*4; i += 256) dst[i] = src[i];
    }

    ull q[16];
    #pragma unroll
    for (int j = 0; j < 4; j++) {
        const float4* qp = (const float4*)(g_q + ((size_t)b*L_ + lb + j*256)*8);
        float4 qa = qp[0], qb = qp[1];
        q[4*j+0] = f2pack(qa.x, qa.y); q[4*j+1] = f2pack(qa.z, qa.w);
        q[4*j+2] = f2pack(qb.x, qb.y); q[4*j+3] = f2pack(qb.z, qb.w);
    }
    __syncthreads();

    ull a[16];
    #pragma unroll
    for (int i = 0; i < 16; i++) a[i] = 0ULL;

    const ulonglong2* kvp = (const ulonglong2*)skv;

    #pragma unroll 2
    for (int m = 0; m < MPART; m++) {
        ulonglong2 kA = kvp[m*4+0];   // uniform address -> broadcast, conflict-free
        ulonglong2 kB = kvp[m*4+1];
        ulonglong2 vA = kvp[m*4+2];
        ulonglong2 vB = kvp[m*4+3];
        #pragma unroll
        for (int j = 0; j < 4; j++) {
            ull d = f2fma(q[4*j+0], kA.x, f2fma(q[4*j+1], kA.y,
                    f2fma(q[4*j+2], kB.x, f2mul(q[4*j+3], kB.y))));
            float lo, hi; f2unpack(d, lo, hi);
            float s = frcp(1.f + fex2(lo + hi));   // sigmoid(Q.K), -log2e folded in Q
            ull s2 = f2pack(s, s);
            a[4*j+0] = f2fma(s2, vA.x, a[4*j+0]);
            a[4*j+1] = f2fma(s2, vA.y, a[4*j+1]);
            a[4*j+2] = f2fma(s2, vB.x, a[4*j+2]);
            a[4*j+3] = f2fma(s2, vB.y, a[4*j+3]);
        }
    }

    #pragma unroll
    for (int j = 0; j < 4; j++) {
        ulonglong2* op = (ulonglong2*)(g_part + ((size_t)mp*P_ + (size_t)b*L_ + lb + j*256)*8);
        ulonglong2 w0; w0.x = a[4*j+0]; w0.y = a[4*j+1];
        ulonglong2 w1; w1.x = a[4*j+2]; w1.y = a[4*j+3];
        op[0] = w0; op[1] = w1;
    }
}

// ============================================================
// Kernel 4: combine 40 partials + threshold_relu + fco -> out (b,2,t,n)
// 4 threads per point: (h = vector half) x (sh = partial half)
// ============================================================
__global__ void __launch_bounds__(256) k_combine(
    const float* __restrict__ fco_w, const float* __restrict__ fco_b, float* __restrict__ out)
{
    const int idx = blockIdx.x*256 + threadIdx.x;
    const int p  = idx >> 2;
    const int h  = idx & 1;        // which float4 half of the 8-vector
    const int sh = (idx >> 1) & 1; // which half of the partials

    float o0=0.f, o1=0.f, o2=0.f, o3=0.f;
    #pragma unroll
    for (int i = 0; i < NPART/2; i++) {
        const int s = sh*(NPART/2) + i;
        float4 a = *(const float4*)(g_part + (((size_t)s*P_ + p)*8) + h*4);
        o0 += a.x; o1 += a.y; o2 += a.z; o3 += a.w;
    }
    // combine partial halves (lanes differing in bit 1)
    o0 += __shfl_xor_sync(0xffffffffu, o0, 2);
    o1 += __shfl_xor_sync(0xffffffffu, o1, 2);
    o2 += __shfl_xor_sync(0xffffffffu, o2, 2);
    o3 += __shfl_xor_sync(0xffffffffu, o3, 2);

    o0 = (o0 > 0.5f) ? o0 : 0.f;
    o1 = (o1 > 0.5f) ? o1 : 0.f;
    o2 = (o2 > 0.5f) ? o2 : 0.f;
    o3 = (o3 > 0.5f) ? o3 : 0.f;

    const float* w0 = fco_w + h*4;
    const float* w1 = fco_w + 8 + h*4;
    float c0 = w0[0]*o0 + w0[1]*o1 + w0[2]*o2 + w0[3]*o3;
    float c1 = w1[0]*o0 + w1[1]*o1 + w1[2]*o2 + w1[3]*o3;
    c0 += __shfl_xor_sync(0xffffffffu, c0, 1);   // combine vector halves
    c1 += __shfl_xor_sync(0xffffffffu, c1, 1);

    if (sh == 0) {
        const int b = p / L_;
        const int l = p % L_;
        const int t = l / N_;
        const int n = l % N_;
        if (h == 0) out[((b*2+0)*T_ + t)*N_ + n] = c0 + fco_b[0];
        else        out[((b*2+1)*T_ + t)*N_ + n] = c1 + fco_b[1];
    }
}

// ============================================================
extern "C" void kernel_launch(void* const* d_in, const int* in_sizes, int n_in,
                              void* d_out, int out_size)
{
    const float* x      = (const float*)d_in[0];
    const float* md     = (const float*)d_in[1];
    const float* w_ih   = (const float*)d_in[2];
    const float* b_ih   = (const float*)d_in[3];
    const float* b_hh   = (const float*)d_in[4];
    const float* comp_w = (const float*)d_in[5];
    const float* comp_b = (const float*)d_in[6];
    const float* vf_w   = (const float*)d_in[7];
    const float* vf_b   = (const float*)d_in[8];
    const float* fc_w   = (const float*)d_in[9];
    const float* fc_b   = (const float*)d_in[10];
    const float* fc2_w  = (const float*)d_in[11];
    const float* fc2_b  = (const float*)d_in[12];
    const float* fc3_w  = (const float*)d_in[13];
    const float* fc3_b  = (const float*)d_in[14];
    const float* fco_w  = (const float*)d_in[15];
    const float* fco_b  = (const float*)d_in[16];
    float* out = (float*)d_out;

    k_compress<<<128, 256>>>(md, comp_w, comp_b, vf_w);
    k_points<<<P_/256, 256>>>(x, w_ih, b_ih, b_hh, vf_w, vf_b,
                              fc_w, fc_b, fc2_w, fc2_b, fc3_w, fc3_b);
    k_attn<<<dim3(L_/1024, NPART, B_), 256>>>();
    k_combine<<<(P_*4)/256, 256>>>(fco_w, fco_b, out);
}

// round 4
// speedup vs baseline: 2.1978x; 1.5654x over previous
#include <cuda_runtime.h>
#include <math.h>

// ---- problem dims (fixed) ----
#define B_    4
#define T_    20
#define N_    256
#define L_    (T_*N_)    // 5120
#define P_    (B_*L_)    // 20480
#define CMAP_ 2048
#define NPART 32
#define MPART 160        // 5120 / 32

typedef unsigned long long ull;

// ---- device scratch ----
__device__ float g_cm4 [4*B_*256*4];   // per-c-part vf-projected feature map
__device__ float g_abc [P_*4];         // per-query (alpha,beta,gamma,0), -log2e folded
__device__ float g_xr  [P_*2];         // per-point PE-shifted coords (xr0,xr1)
__device__ float g_part[NPART*(size_t)P_*4];  // per-part (t0,t1,t2,0)

// ---- helpers ----
__device__ __forceinline__ ull f2pack(float a, float b){ ull r; asm("mov.b64 %0,{%1,%2};":"=l"(r):"f"(a),"f"(b)); return r; }
__device__ __forceinline__ ull f2fma(ull a, ull b, ull c){ ull d; asm("fma.rn.f32x2 %0,%1,%2,%3;":"=l"(d):"l"(a),"l"(b),"l"(c)); return d; }
__device__ __forceinline__ float fex2(float x){ float r; asm("ex2.approx.f32 %0,%1;":"=f"(r):"f"(x)); return r; }
__device__ __forceinline__ float frcp(float x){ float r; asm("rcp.approx.f32 %0,%1;":"=f"(r):"f"(x)); return r; }
__device__ __forceinline__ float sigf(float x){ return 1.f/(1.f+expf(-x)); }

// ============================================================
// Kernel 1: compressor + folded vf projection (unchanged)
// ============================================================
__global__ void __launch_bounds__(256) k_compress(
    const float* __restrict__ md, const float* __restrict__ cw, const float* __restrict__ cb,
    const float* __restrict__ vf_w)
{
    __shared__ float wT[256][36];
    __shared__ float cm32[32][33];

    const int cpart = blockIdx.x & 3;
    const int tile  = (blockIdx.x >> 2) & 7;
    const int b     = blockIdx.x >> 5;
    const int tid  = threadIdx.x;
    const int lane = tid & 31;
    const int warp = tid >> 5;
    const int hw   = tile*32 + lane;

    ull acc[16];
    #pragma unroll
    for (int i=0;i<16;i++) acc[i] = 0ULL;

    #pragma unroll
    for (int chunk = 0; chunk < 2; chunk++) {
        const int cb0 = cpart*512 + chunk*256;
        __syncthreads();
        #pragma unroll 4
        for (int r = 0; r < 32; r++)
            wT[tid][r] = cw[r*CMAP_ + cb0 + tid];
        __syncthreads();

        const int cl0 = warp*32;
        #pragma unroll 4
        for (int k = 0; k < 32; k++) {
            const int cl = cl0 + k;
            float m = md[(size_t)(b*CMAP_ + cb0 + cl)*256 + hw];
            ull m2 = f2pack(m, m);
            const ulonglong2* wrow = (const ulonglong2*)(&wT[cl][0]);
            #pragma unroll
            for (int i = 0; i < 8; i++) {
                ulonglong2 wv = wrow[i];
                acc[2*i]   = f2fma(m2, wv.x, acc[2*i]);
                acc[2*i+1] = f2fma(m2, wv.y, acc[2*i+1]);
            }
        }
    }

    __syncthreads();
    {
        ull* row = (ull*)&wT[tid][0];
        #pragma unroll
        for (int i = 0; i < 16; i++) row[i] = acc[i];
    }
    __syncthreads();

    const int hwl = tid & 31;
    const int og  = tid >> 5;
    float r0=0.f, r1=0.f, r2=0.f, r3=0.f;
    #pragma unroll
    for (int w2 = 0; w2 < 8; w2++) {
        const float* rr = &wT[w2*32 + hwl][og*4];
        r0 += rr[0]; r1 += rr[1]; r2 += rr[2]; r3 += rr[3];
    }
    if (cpart == 0) {
        r0 += cb[og*4+0]; r1 += cb[og*4+1]; r2 += cb[og*4+2]; r3 += cb[og*4+3];
    }
    cm32[hwl][og*4+0] = r0; cm32[hwl][og*4+1] = r1;
    cm32[hwl][og*4+2] = r2; cm32[hwl][og*4+3] = r3;
    __syncthreads();

    if (og < 4) {
        float s = 0.f;
        #pragma unroll
        for (int j = 0; j < 32; j++)
            s = fmaf(vf_w[og*36 + 4 + j], cm32[hwl][j], s);
        g_cm4[(((size_t)cpart*B_ + b)*256 + tile*32 + hwl)*4 + og] = s;
    }
}

// ============================================================
// Kernel 2: per-point prep — now emits (xr0,xr1) and (alpha,beta,gamma)
// alpha = -log2e * Q.fc2_b ; beta = -log2e * Q.fc2_w[:,0] ; gamma = ...[:,1]
// ============================================================
__global__ void __launch_bounds__(256) k_points(
    const float* __restrict__ x,
    const float* __restrict__ w_ih, const float* __restrict__ b_ih, const float* __restrict__ b_hh,
    const float* __restrict__ vf_w, const float* __restrict__ vf_b,
    const float* __restrict__ fc_w, const float* __restrict__ fc_b,
    const float* __restrict__ fc2_w, const float* __restrict__ fc2_b)
{
    const int p = blockIdx.x*256 + threadIdx.x;
    const int b = p / L_;
    const int l = p % L_;
    const int t = l / N_;
    const int n = l % N_;

    const float x0 = x[((b*2+0)*T_ + t)*N_ + n];
    const float x1 = x[((b*2+1)*T_ + t)*N_ + n];
    const float ft = (float)t;
    const float xr0 = x0 + sinf(ft);
    const float xr1 = x1 + cosf(ft);

    // single-step LSTM (h0=c0=0)
    float X[4];
    #pragma unroll
    for (int j = 0; j < 4; j++) {
        float ig = fmaf(w_ih[2*j],      xr0, fmaf(w_ih[2*j+1],      xr1, b_ih[j]    + b_hh[j]));
        float gg = fmaf(w_ih[2*(8+j)],  xr0, fmaf(w_ih[2*(8+j)+1],  xr1, b_ih[8+j]  + b_hh[8+j]));
        float og = fmaf(w_ih[2*(12+j)], xr0, fmaf(w_ih[2*(12+j)+1], xr1, b_ih[12+j] + b_hh[12+j]));
        float c  = sigf(ig)*tanhf(gg);
        X[j] = sigf(og)*tanhf(c);
    }

    // bilinear sample of projected maps
    const float ix = x0*(1.f/32.f) - 0.5f;
    const float iy = x1*(1.f/32.f) - 0.5f;
    const float x0f = floorf(ix), y0f = floorf(iy);
    const float wx1 = ix - x0f, wx0 = 1.f - wx1;
    const float wy1 = iy - y0f, wy0 = 1.f - wy1;
    const int xi0 = (int)x0f, yi0 = (int)y0f;

    float lcp0=0.f, lcp1=0.f, lcp2=0.f, lcp3=0.f;
    #pragma unroll
    for (int cy = 0; cy < 2; cy++) {
        #pragma unroll
        for (int cx = 0; cx < 2; cx++) {
            const int xi = xi0 + cx, yi = yi0 + cy;
            const float wgt = (cx ? wx1 : wx0) * (cy ? wy1 : wy0);
            if (xi >= 0 && xi < 16 && yi >= 0 && yi < 16) {
                #pragma unroll
                for (int part = 0; part < 4; part++) {
                    float4 v = *(const float4*)&g_cm4[(((size_t)part*B_ + b)*256 + yi*16 + xi)*4];
                    lcp0 = fmaf(wgt, v.x, lcp0);
                    lcp1 = fmaf(wgt, v.y, lcp1);
                    lcp2 = fmaf(wgt, v.z, lcp2);
                    lcp3 = fmaf(wgt, v.w, lcp3);
                }
            }
        }
    }

    float X2[4];
    {
        float lcp[4] = {lcp0, lcp1, lcp2, lcp3};
        #pragma unroll
        for (int i = 0; i < 4; i++) {
            float s = vf_b[i] + lcp[i];
            #pragma unroll
            for (int j = 0; j < 4; j++) s = fmaf(vf_w[i*36+j], X[j], s);
            X2[i] = s;
        }
    }

    // Q then collapse against the rank-2 K factorization
    float alpha = 0.f, beta = 0.f, gamma = 0.f;
    #pragma unroll
    for (int k = 0; k < 8; k++) {
        float q = fc_b[k];
        #pragma unroll
        for (int i = 0; i < 4; i++) q = fmaf(fc_w[k*4+i], X2[i], q);
        alpha = fmaf(q, fc2_b[k],    alpha);
        beta  = fmaf(q, fc2_w[2*k],  beta);
        gamma = fmaf(q, fc2_w[2*k+1],gamma);
    }
    const float NEGL2E = -1.4426950408889634f;
    float4 abc; abc.x = alpha*NEGL2E; abc.y = beta*NEGL2E; abc.z = gamma*NEGL2E; abc.w = 0.f;
    *(float4*)&g_abc[(size_t)p*4] = abc;
    float2 xr; xr.x = xr0; xr.y = xr1;
    *(float2*)&g_xr[(size_t)p*2] = xr;
}

// ============================================================
// Kernel 3: attention partials — rank-collapsed
// per (query, part): t0 = sum s, t1 = sum s*x0, t2 = sum s*x1
// grid (5 l-tiles, 32 m-parts, 4 batches) = 640 blocks, 256 threads, 4 q/thread
// ============================================================
__global__ void __launch_bounds__(256) k_attn()
{
    __shared__ float4 sxr[MPART/2];   // 160 keys -> 80 float4 (x0a,x1a,x0b,x1b)

    const int b  = blockIdx.z;
    const int mp = blockIdx.y;
    const int lb = blockIdx.x*1024 + threadIdx.x;

    if (threadIdx.x < MPART/2)
        sxr[threadIdx.x] = ((const float4*)(g_xr + ((size_t)b*L_ + (size_t)mp*MPART)*2))[threadIdx.x];

    float al[4], be[4], ga[4];
    #pragma unroll
    for (int j = 0; j < 4; j++) {
        float4 abc = *(const float4*)&g_abc[((size_t)b*L_ + lb + j*256)*4];
        al[j] = abc.x; be[j] = abc.y; ga[j] = abc.z;
    }
    __syncthreads();

    float t0[4], t1[4], t2[4];
    #pragma unroll
    for (int j = 0; j < 4; j++) { t0[j]=0.f; t1[j]=0.f; t2[j]=0.f; }

    #pragma unroll 2
    for (int mm = 0; mm < MPART/2; mm++) {
        float4 xv = sxr[mm];   // two keys, broadcast LDS.128
        #pragma unroll
        for (int j = 0; j < 4; j++) {
            float za = fmaf(be[j], xv.x, fmaf(ga[j], xv.y, al[j]));
            float sa = frcp(1.f + fex2(za));
            t0[j] += sa;
            t1[j]  = fmaf(sa, xv.x, t1[j]);
            t2[j]  = fmaf(sa, xv.y, t2[j]);
            float zb = fmaf(be[j], xv.z, fmaf(ga[j], xv.w, al[j]));
            float sb = frcp(1.f + fex2(zb));
            t0[j] += sb;
            t1[j]  = fmaf(sb, xv.z, t1[j]);
            t2[j]  = fmaf(sb, xv.w, t2[j]);
        }
    }

    #pragma unroll
    for (int j = 0; j < 4; j++) {
        float4 w; w.x = t0[j]; w.y = t1[j]; w.z = t2[j]; w.w = 0.f;
        *(float4*)&g_part[((size_t)mp*P_ + (size_t)b*L_ + lb + j*256)*4] = w;
    }
}

// ============================================================
// Kernel 4: combine + rank-3 V reconstruct + threshold + fco -> out
// 4 threads per query, each sums 8 parts, shfl-reduce, lane sub==0 writes
// ============================================================
__global__ void __launch_bounds__(256) k_combine(
    const float* __restrict__ fc3_w, const float* __restrict__ fc3_b,
    const float* __restrict__ fco_w, const float* __restrict__ fco_b,
    float* __restrict__ out)
{
    const int idx = blockIdx.x*256 + threadIdx.x;
    const int p   = idx >> 2;
    const int sub = idx & 3;

    float t0=0.f, t1=0.f, t2=0.f;
    #pragma unroll
    for (int i = 0; i < NPART/4; i++) {
        const int s = sub*(NPART/4) + i;
        float4 a = *(const float4*)&g_part[((size_t)s*P_ + p)*4];
        t0 += a.x; t1 += a.y; t2 += a.z;
    }
    t0 += __shfl_xor_sync(0xffffffffu, t0, 1);
    t1 += __shfl_xor_sync(0xffffffffu, t1, 1);
    t2 += __shfl_xor_sync(0xffffffffu, t2, 1);
    t0 += __shfl_xor_sync(0xffffffffu, t0, 2);
    t1 += __shfl_xor_sync(0xffffffffu, t1, 2);
    t2 += __shfl_xor_sync(0xffffffffu, t2, 2);

    if (sub == 0) {
        float r0 = fco_b[0], r1 = fco_b[1];
        #pragma unroll
        for (int i = 0; i < 8; i++) {
            float o = fmaf(t0, fc3_b[i], fmaf(t1, fc3_w[2*i], t2*fc3_w[2*i+1]));
            o = (o > 0.5f) ? o : 0.f;
            r0 = fmaf(fco_w[i],   o, r0);
            r1 = fmaf(fco_w[8+i], o, r1);
        }
        const int b = p / L_;
        const int l = p % L_;
        const int t = l / N_;
        const int n = l % N_;
        out[((b*2+0)*T_ + t)*N_ + n] = r0;
        out[((b*2+1)*T_ + t)*N_ + n] = r1;
    }
}

// ============================================================
extern "C" void kernel_launch(void* const* d_in, const int* in_sizes, int n_in,
                              void* d_out, int out_size)
{
    const float* x      = (const float*)d_in[0];
    const float* md     = (const float*)d_in[1];
    const float* w_ih   = (const float*)d_in[2];
    const float* b_ih   = (const float*)d_in[3];
    const float* b_hh   = (const float*)d_in[4];
    const float* comp_w = (const float*)d_in[5];
    const float* comp_b = (const float*)d_in[6];
    const float* vf_w   = (const float*)d_in[7];
    const float* vf_b   = (const float*)d_in[8];
    const float* fc_w   = (const float*)d_in[9];
    const float* fc_b   = (const float*)d_in[10];
    const float* fc2_w  = (const float*)d_in[11];
    const float* fc2_b  = (const float*)d_in[12];
    const float* fc3_w  = (const float*)d_in[13];
    const float* fc3_b  = (const float*)d_in[14];
    const float* fco_w  = (const float*)d_in[15];
    const float* fco_b  = (const float*)d_in[16];
    float* out = (float*)d_out;

    k_compress<<<128, 256>>>(md, comp_w, comp_b, vf_w);
    k_points<<<P_/256, 256>>>(x, w_ih, b_ih, b_hh, vf_w, vf_b,
                              fc_w, fc_b, fc2_w, fc2_b);
    k_attn<<<dim3(L_/1024, NPART, B_), 256>>>();
    k_combine<<<(P_*4)/256, 256>>>(fc3_w, fc3_b, fco_w, fco_b, out);
}

// round 5
// speedup vs baseline: 2.1987x; 1.0004x over previous
#include <cuda_runtime.h>
#include <math.h>

// ---- problem dims (fixed) ----
#define B_    4
#define T_    20
#define N_    256
#define L_    (T_*N_)    // 5120
#define P_    (B_*L_)    // 20480
#define CMAP_ 2048
#define NPART 32
#define MPART 160        // 5120 / 32

typedef unsigned long long ull;

// ---- device scratch ----
__device__ float g_cm4 [4*B_*256*4];   // per-c-part vf-projected feature map
__device__ float g_abc [P_*4];         // per-query (alpha,beta,gamma,0), -log2e folded
__device__ float g_xr  [P_*2];         // per-point PE-shifted coords (xr0,xr1)
__device__ float g_part[NPART*(size_t)P_*4];  // per-part (t0,t1,t2,0)

// ---- helpers ----
__device__ __forceinline__ ull f2pack(float a, float b){ ull r; asm("mov.b64 %0,{%1,%2};":"=l"(r):"f"(a),"f"(b)); return r; }
__device__ __forceinline__ ull f2fma(ull a, ull b, ull c){ ull d; asm("fma.rn.f32x2 %0,%1,%2,%3;":"=l"(d):"l"(a),"l"(b),"l"(c)); return d; }
__device__ __forceinline__ float fex2(float x){ float r; asm("ex2.approx.f32 %0,%1;":"=f"(r):"f"(x)); return r; }
__device__ __forceinline__ float frcp(float x){ float r; asm("rcp.approx.f32 %0,%1;":"=f"(r):"f"(x)); return r; }
__device__ __forceinline__ float sigf(float x){ return 1.f/(1.f+expf(-x)); }

// ============================================================
// Kernel 1: compressor + folded vf projection (unchanged)
// ============================================================
__global__ void __launch_bounds__(256) k_compress(
    const float* __restrict__ md, const float* __restrict__ cw, const float* __restrict__ cb,
    const float* __restrict__ vf_w)
{
    __shared__ float wT[256][36];
    __shared__ float cm32[32][33];

    const int cpart = blockIdx.x & 3;
    const int tile  = (blockIdx.x >> 2) & 7;
    const int b     = blockIdx.x >> 5;
    const int tid  = threadIdx.x;
    const int lane = tid & 31;
    const int warp = tid >> 5;
    const int hw   = tile*32 + lane;

    ull acc[16];
    #pragma unroll
    for (int i=0;i<16;i++) acc[i] = 0ULL;

    #pragma unroll
    for (int chunk = 0; chunk < 2; chunk++) {
        const int cb0 = cpart*512 + chunk*256;
        __syncthreads();
        #pragma unroll 4
        for (int r = 0; r < 32; r++)
            wT[tid][r] = cw[r*CMAP_ + cb0 + tid];
        __syncthreads();

        const int cl0 = warp*32;
        #pragma unroll 4
        for (int k = 0; k < 32; k++) {
            const int cl = cl0 + k;
            float m = md[(size_t)(b*CMAP_ + cb0 + cl)*256 + hw];
            ull m2 = f2pack(m, m);
            const ulonglong2* wrow = (const ulonglong2*)(&wT[cl][0]);
            #pragma unroll
            for (int i = 0; i < 8; i++) {
                ulonglong2 wv = wrow[i];
                acc[2*i]   = f2fma(m2, wv.x, acc[2*i]);
                acc[2*i+1] = f2fma(m2, wv.y, acc[2*i+1]);
            }
        }
    }

    __syncthreads();
    {
        ull* row = (ull*)&wT[tid][0];
        #pragma unroll
        for (int i = 0; i < 16; i++) row[i] = acc[i];
    }
    __syncthreads();

    const int hwl = tid & 31;
    const int og  = tid >> 5;
    float r0=0.f, r1=0.f, r2=0.f, r3=0.f;
    #pragma unroll
    for (int w2 = 0; w2 < 8; w2++) {
        const float* rr = &wT[w2*32 + hwl][og*4];
        r0 += rr[0]; r1 += rr[1]; r2 += rr[2]; r3 += rr[3];
    }
    if (cpart == 0) {
        r0 += cb[og*4+0]; r1 += cb[og*4+1]; r2 += cb[og*4+2]; r3 += cb[og*4+3];
    }
    cm32[hwl][og*4+0] = r0; cm32[hwl][og*4+1] = r1;
    cm32[hwl][og*4+2] = r2; cm32[hwl][og*4+3] = r3;
    __syncthreads();

    if (og < 4) {
        float s = 0.f;
        #pragma unroll
        for (int j = 0; j < 32; j++)
            s = fmaf(vf_w[og*36 + 4 + j], cm32[hwl][j], s);
        g_cm4[(((size_t)cpart*B_ + b)*256 + tile*32 + hwl)*4 + og] = s;
    }
}

// ============================================================
// Kernel 2: per-point prep — now emits (xr0,xr1) and (alpha,beta,gamma)
// alpha = -log2e * Q.fc2_b ; beta = -log2e * Q.fc2_w[:,0] ; gamma = ...[:,1]
// ============================================================
__global__ void __launch_bounds__(256) k_points(
    const float* __restrict__ x,
    const float* __restrict__ w_ih, const float* __restrict__ b_ih, const float* __restrict__ b_hh,
    const float* __restrict__ vf_w, const float* __restrict__ vf_b,
    const float* __restrict__ fc_w, const float* __restrict__ fc_b,
    const float* __restrict__ fc2_w, const float* __restrict__ fc2_b)
{
    const int p = blockIdx.x*256 + threadIdx.x;
    const int b = p / L_;
    const int l = p % L_;
    const int t = l / N_;
    const int n = l % N_;

    const float x0 = x[((b*2+0)*T_ + t)*N_ + n];
    const float x1 = x[((b*2+1)*T_ + t)*N_ + n];
    const float ft = (float)t;
    const float xr0 = x0 + sinf(ft);
    const float xr1 = x1 + cosf(ft);

    // single-step LSTM (h0=c0=0)
    float X[4];
    #pragma unroll
    for (int j = 0; j < 4; j++) {
        float ig = fmaf(w_ih[2*j],      xr0, fmaf(w_ih[2*j+1],      xr1, b_ih[j]    + b_hh[j]));
        float gg = fmaf(w_ih[2*(8+j)],  xr0, fmaf(w_ih[2*(8+j)+1],  xr1, b_ih[8+j]  + b_hh[8+j]));
        float og = fmaf(w_ih[2*(12+j)], xr0, fmaf(w_ih[2*(12+j)+1], xr1, b_ih[12+j] + b_hh[12+j]));
        float c  = sigf(ig)*tanhf(gg);
        X[j] = sigf(og)*tanhf(c);
    }

    // bilinear sample of projected maps
    const float ix = x0*(1.f/32.f) - 0.5f;
    const float iy = x1*(1.f/32.f) - 0.5f;
    const float x0f = floorf(ix), y0f = floorf(iy);
    const float wx1 = ix - x0f, wx0 = 1.f - wx1;
    const float wy1 = iy - y0f, wy0 = 1.f - wy1;
    const int xi0 = (int)x0f, yi0 = (int)y0f;

    float lcp0=0.f, lcp1=0.f, lcp2=0.f, lcp3=0.f;
    #pragma unroll
    for (int cy = 0; cy < 2; cy++) {
        #pragma unroll
        for (int cx = 0; cx < 2; cx++) {
            const int xi = xi0 + cx, yi = yi0 + cy;
            const float wgt = (cx ? wx1 : wx0) * (cy ? wy1 : wy0);
            if (xi >= 0 && xi < 16 && yi >= 0 && yi < 16) {
                #pragma unroll
                for (int part = 0; part < 4; part++) {
                    float4 v = *(const float4*)&g_cm4[(((size_t)part*B_ + b)*256 + yi*16 + xi)*4];
                    lcp0 = fmaf(wgt, v.x, lcp0);
                    lcp1 = fmaf(wgt, v.y, lcp1);
                    lcp2 = fmaf(wgt, v.z, lcp2);
                    lcp3 = fmaf(wgt, v.w, lcp3);
                }
            }
        }
    }

    float X2[4];
    {
        float lcp[4] = {lcp0, lcp1, lcp2, lcp3};
        #pragma unroll
        for (int i = 0; i < 4; i++) {
            float s = vf_b[i] + lcp[i];
            #pragma unroll
            for (int j = 0; j < 4; j++) s = fmaf(vf_w[i*36+j], X[j], s);
            X2[i] = s;
        }
    }

    // Q then collapse against the rank-2 K factorization
    float alpha = 0.f, beta = 0.f, gamma = 0.f;
    #pragma unroll
    for (int k = 0; k < 8; k++) {
        float q = fc_b[k];
        #pragma unroll
        for (int i = 0; i < 4; i++) q = fmaf(fc_w[k*4+i], X2[i], q);
        alpha = fmaf(q, fc2_b[k],    alpha);
        beta  = fmaf(q, fc2_w[2*k],  beta);
        gamma = fmaf(q, fc2_w[2*k+1],gamma);
    }
    const float NEGL2E = -1.4426950408889634f;
    float4 abc; abc.x = alpha*NEGL2E; abc.y = beta*NEGL2E; abc.z = gamma*NEGL2E; abc.w = 0.f;
    *(float4*)&g_abc[(size_t)p*4] = abc;
    float2 xr; xr.x = xr0; xr.y = xr1;
    *(float2*)&g_xr[(size_t)p*2] = xr;
}

// ============================================================
// Kernel 3: attention partials — rank-collapsed
// per (query, part): t0 = sum s, t1 = sum s*x0, t2 = sum s*x1
// grid (5 l-tiles, 32 m-parts, 4 batches) = 640 blocks, 256 threads, 4 q/thread
// ============================================================
__global__ void __launch_bounds__(256) k_attn()
{
    __shared__ float4 sxr[MPART/2];   // 160 keys -> 80 float4 (x0a,x1a,x0b,x1b)

    const int b  = blockIdx.z;
    const int mp = blockIdx.y;
    const int lb = blockIdx.x*1024 + threadIdx.x;

    if (threadIdx.x < MPART/2)
        sxr[threadIdx.x] = ((const float4*)(g_xr + ((size_t)b*L_ + (size_t)mp*MPART)*2))[threadIdx.x];

    float al[4], be[4], ga[4];
    #pragma unroll
    for (int j = 0; j < 4; j++) {
        float4 abc = *(const float4*)&g_abc[((size_t)b*L_ + lb + j*256)*4];
        al[j] = abc.x; be[j] = abc.y; ga[j] = abc.z;
    }
    __syncthreads();

    float t0[4], t1[4], t2[4];
    #pragma unroll
    for (int j = 0; j < 4; j++) { t0[j]=0.f; t1[j]=0.f; t2[j]=0.f; }

    #pragma unroll 2
    for (int mm = 0; mm < MPART/2; mm++) {
        float4 xv = sxr[mm];   // two keys, broadcast LDS.128
        #pragma unroll
        for (int j = 0; j < 4; j++) {
            float za = fmaf(be[j], xv.x, fmaf(ga[j], xv.y, al[j]));
            float sa = frcp(1.f + fex2(za));
            t0[j] += sa;
            t1[j]  = fmaf(sa, xv.x, t1[j]);
            t2[j]  = fmaf(sa, xv.y, t2[j]);
            float zb = fmaf(be[j], xv.z, fmaf(ga[j], xv.w, al[j]));
            float sb = frcp(1.f + fex2(zb));
            t0[j] += sb;
            t1[j]  = fmaf(sb, xv.z, t1[j]);
            t2[j]  = fmaf(sb, xv.w, t2[j]);
        }
    }

    #pragma unroll
    for (int j = 0; j < 4; j++) {
        float4 w; w.x = t0[j]; w.y = t1[j]; w.z = t2[j]; w.w = 0.f;
        *(float4*)&g_part[((size_t)mp*P_ + (size_t)b*L_ + lb + j*256)*4] = w;
    }
}

// ============================================================
// Kernel 4: combine + rank-3 V reconstruct + threshold + fco -> out
// 4 threads per query, each sums 8 parts, shfl-reduce, lane sub==0 writes
// ============================================================
__global__ void __launch_bounds__(256) k_combine(
    const float* __restrict__ fc3_w, const float* __restrict__ fc3_b,
    const float* __restrict__ fco_w, const float* __restrict__ fco_b,
    float* __restrict__ out)
{
    const int idx = blockIdx.x*256 + threadIdx.x;
    const int p   = idx >> 2;
    const int sub = idx & 3;

    float t0=0.f, t1=0.f, t2=0.f;
    #pragma unroll
    for (int i = 0; i < NPART/4; i++) {
        const int s = sub*(NPART/4) + i;
        float4 a = *(const float4*)&g_part[((size_t)s*P_ + p)*4];
        t0 += a.x; t1 += a.y; t2 += a.z;
    }
    t0 += __shfl_xor_sync(0xffffffffu, t0, 1);
    t1 += __shfl_xor_sync(0xffffffffu, t1, 1);
    t2 += __shfl_xor_sync(0xffffffffu, t2, 1);
    t0 += __shfl_xor_sync(0xffffffffu, t0, 2);
    t1 += __shfl_xor_sync(0xffffffffu, t1, 2);
    t2 += __shfl_xor_sync(0xffffffffu, t2, 2);

    if (sub == 0) {
        float r0 = fco_b[0], r1 = fco_b[1];
        #pragma unroll
        for (int i = 0; i < 8; i++) {
            float o = fmaf(t0, fc3_b[i], fmaf(t1, fc3_w[2*i], t2*fc3_w[2*i+1]));
            o = (o > 0.5f) ? o : 0.f;
            r0 = fmaf(fco_w[i],   o, r0);
            r1 = fmaf(fco_w[8+i], o, r1);
        }
        const int b = p / L_;
        const int l = p % L_;
        const int t = l / N_;
        const int n = l % N_;
        out[((b*2+0)*T_ + t)*N_ + n] = r0;
        out[((b*2+1)*T_ + t)*N_ + n] = r1;
    }
}

// ============================================================
extern "C" void kernel_launch(void* const* d_in, const int* in_sizes, int n_in,
                              void* d_out, int out_size)
{
    const float* x      = (const float*)d_in[0];
    const float* md     = (const float*)d_in[1];
    const float* w_ih   = (const float*)d_in[2];
    const float* b_ih   = (const float*)d_in[3];
    const float* b_hh   = (const float*)d_in[4];
    const float* comp_w = (const float*)d_in[5];
    const float* comp_b = (const float*)d_in[6];
    const float* vf_w   = (const float*)d_in[7];
    const float* vf_b   = (const float*)d_in[8];
    const float* fc_w   = (const float*)d_in[9];
    const float* fc_b   = (const float*)d_in[10];
    const float* fc2_w  = (const float*)d_in[11];
    const float* fc2_b  = (const float*)d_in[12];
    const float* fc3_w  = (const float*)d_in[13];
    const float* fc3_b  = (const float*)d_in[14];
    const float* fco_w  = (const float*)d_in[15];
    const float* fco_b  = (const float*)d_in[16];
    float* out = (float*)d_out;

    k_compress<<<128, 256>>>(md, comp_w, comp_b, vf_w);
    k_points<<<P_/256, 256>>>(x, w_ih, b_ih, b_hh, vf_w, vf_b,
                              fc_w, fc_b, fc2_w, fc2_b);
    k_attn<<<dim3(L_/1024, NPART, B_), 256>>>();
    k_combine<<<(P_*4)/256, 256>>>(fc3_w, fc3_b, fco_w, fco_b, out);
}

// round 6
// speedup vs baseline: 2.2108x; 1.0055x over previous
#include <cuda_runtime.h>
#include <math.h>

// ---- problem dims (fixed) ----
#define B_    4
#define T_    20
#define N_    256
#define L_    (T_*N_)    // 5120
#define P_    (B_*L_)    // 20480
#define CMAP_ 2048
#define NPART 32
#define MPART 160        // 5120 / 32

typedef unsigned long long ull;

// ---- device scratch ----
__device__ float g_cm4 [4*B_*256*4];   // per-c-part vf-projected feature map
__device__ float g_abc [P_*4];         // per-query (alpha,beta,gamma,0), -log2e folded
__device__ float g_xr  [P_*2];         // per-point PE-shifted coords (xr0,xr1)
__device__ float g_part[NPART*(size_t)P_*4];  // per-part (t0,t1,t2,0)

// ---- helpers ----
__device__ __forceinline__ ull f2pack(float a, float b){ ull r; asm("mov.b64 %0,{%1,%2};":"=l"(r):"f"(a),"f"(b)); return r; }
__device__ __forceinline__ ull f2fma(ull a, ull b, ull c){ ull d; asm("fma.rn.f32x2 %0,%1,%2,%3;":"=l"(d):"l"(a),"l"(b),"l"(c)); return d; }
__device__ __forceinline__ float fex2(float x){ float r; asm("ex2.approx.f32 %0,%1;":"=f"(r):"f"(x)); return r; }
__device__ __forceinline__ float frcp(float x){ float r; asm("rcp.approx.f32 %0,%1;":"=f"(r):"f"(x)); return r; }
__device__ __forceinline__ float sigf(float x){ return 1.f/(1.f+expf(-x)); }

// ============================================================
// Kernel 1: compressor + folded vf projection (unchanged)
// ============================================================
__global__ void __launch_bounds__(256) k_compress(
    const float* __restrict__ md, const float* __restrict__ cw, const float* __restrict__ cb,
    const float* __restrict__ vf_w)
{
    __shared__ float wT[256][36];
    __shared__ float cm32[32][33];

    const int cpart = blockIdx.x & 3;
    const int tile  = (blockIdx.x >> 2) & 7;
    const int b     = blockIdx.x >> 5;
    const int tid  = threadIdx.x;
    const int lane = tid & 31;
    const int warp = tid >> 5;
    const int hw   = tile*32 + lane;

    ull acc[16];
    #pragma unroll
    for (int i=0;i<16;i++) acc[i] = 0ULL;

    #pragma unroll
    for (int chunk = 0; chunk < 2; chunk++) {
        const int cb0 = cpart*512 + chunk*256;
        __syncthreads();
        #pragma unroll 4
        for (int r = 0; r < 32; r++)
            wT[tid][r] = cw[r*CMAP_ + cb0 + tid];
        __syncthreads();

        const int cl0 = warp*32;
        #pragma unroll 4
        for (int k = 0; k < 32; k++) {
            const int cl = cl0 + k;
            float m = md[(size_t)(b*CMAP_ + cb0 + cl)*256 + hw];
            ull m2 = f2pack(m, m);
            const ulonglong2* wrow = (const ulonglong2*)(&wT[cl][0]);
            #pragma unroll
            for (int i = 0; i < 8; i++) {
                ulonglong2 wv = wrow[i];
                acc[2*i]   = f2fma(m2, wv.x, acc[2*i]);
                acc[2*i+1] = f2fma(m2, wv.y, acc[2*i+1]);
            }
        }
    }

    __syncthreads();
    {
        ull* row = (ull*)&wT[tid][0];
        #pragma unroll
        for (int i = 0; i < 16; i++) row[i] = acc[i];
    }
    __syncthreads();

    const int hwl = tid & 31;
    const int og  = tid >> 5;
    float r0=0.f, r1=0.f, r2=0.f, r3=0.f;
    #pragma unroll
    for (int w2 = 0; w2 < 8; w2++) {
        const float* rr = &wT[w2*32 + hwl][og*4];
        r0 += rr[0]; r1 += rr[1]; r2 += rr[2]; r3 += rr[3];
    }
    if (cpart == 0) {
        r0 += cb[og*4+0]; r1 += cb[og*4+1]; r2 += cb[og*4+2]; r3 += cb[og*4+3];
    }
    cm32[hwl][og*4+0] = r0; cm32[hwl][og*4+1] = r1;
    cm32[hwl][og*4+2] = r2; cm32[hwl][og*4+3] = r3;
    __syncthreads();

    if (og < 4) {
        float s = 0.f;
        #pragma unroll
        for (int j = 0; j < 32; j++)
            s = fmaf(vf_w[og*36 + 4 + j], cm32[hwl][j], s);
        g_cm4[(((size_t)cpart*B_ + b)*256 + tile*32 + hwl)*4 + og] = s;
    }
}

// ============================================================
// Kernel 2: per-point prep — now emits (xr0,xr1) and (alpha,beta,gamma)
// alpha = -log2e * Q.fc2_b ; beta = -log2e * Q.fc2_w[:,0] ; gamma = ...[:,1]
// ============================================================
__global__ void __launch_bounds__(256) k_points(
    const float* __restrict__ x,
    const float* __restrict__ w_ih, const float* __restrict__ b_ih, const float* __restrict__ b_hh,
    const float* __restrict__ vf_w, const float* __restrict__ vf_b,
    const float* __restrict__ fc_w, const float* __restrict__ fc_b,
    const float* __restrict__ fc2_w, const float* __restrict__ fc2_b)
{
    const int p = blockIdx.x*256 + threadIdx.x;
    const int b = p / L_;
    const int l = p % L_;
    const int t = l / N_;
    const int n = l % N_;

    const float x0 = x[((b*2+0)*T_ + t)*N_ + n];
    const float x1 = x[((b*2+1)*T_ + t)*N_ + n];
    const float ft = (float)t;
    const float xr0 = x0 + sinf(ft);
    const float xr1 = x1 + cosf(ft);

    // single-step LSTM (h0=c0=0)
    float X[4];
    #pragma unroll
    for (int j = 0; j < 4; j++) {
        float ig = fmaf(w_ih[2*j],      xr0, fmaf(w_ih[2*j+1],      xr1, b_ih[j]    + b_hh[j]));
        float gg = fmaf(w_ih[2*(8+j)],  xr0, fmaf(w_ih[2*(8+j)+1],  xr1, b_ih[8+j]  + b_hh[8+j]));
        float og = fmaf(w_ih[2*(12+j)], xr0, fmaf(w_ih[2*(12+j)+1], xr1, b_ih[12+j] + b_hh[12+j]));
        float c  = sigf(ig)*tanhf(gg);
        X[j] = sigf(og)*tanhf(c);
    }

    // bilinear sample of projected maps
    const float ix = x0*(1.f/32.f) - 0.5f;
    const float iy = x1*(1.f/32.f) - 0.5f;
    const float x0f = floorf(ix), y0f = floorf(iy);
    const float wx1 = ix - x0f, wx0 = 1.f - wx1;
    const float wy1 = iy - y0f, wy0 = 1.f - wy1;
    const int xi0 = (int)x0f, yi0 = (int)y0f;

    float lcp0=0.f, lcp1=0.f, lcp2=0.f, lcp3=0.f;
    #pragma unroll
    for (int cy = 0; cy < 2; cy++) {
        #pragma unroll
        for (int cx = 0; cx < 2; cx++) {
            const int xi = xi0 + cx, yi = yi0 + cy;
            const float wgt = (cx ? wx1 : wx0) * (cy ? wy1 : wy0);
            if (xi >= 0 && xi < 16 && yi >= 0 && yi < 16) {
                #pragma unroll
                for (int part = 0; part < 4; part++) {
                    float4 v = *(const float4*)&g_cm4[(((size_t)part*B_ + b)*256 + yi*16 + xi)*4];
                    lcp0 = fmaf(wgt, v.x, lcp0);
                    lcp1 = fmaf(wgt, v.y, lcp1);
                    lcp2 = fmaf(wgt, v.z, lcp2);
                    lcp3 = fmaf(wgt, v.w, lcp3);
                }
            }
        }
    }

    float X2[4];
    {
        float lcp[4] = {lcp0, lcp1, lcp2, lcp3};
        #pragma unroll
        for (int i = 0; i < 4; i++) {
            float s = vf_b[i] + lcp[i];
            #pragma unroll
            for (int j = 0; j < 4; j++) s = fmaf(vf_w[i*36+j], X[j], s);
            X2[i] = s;
        }
    }

    // Q then collapse against the rank-2 K factorization
    float alpha = 0.f, beta = 0.f, gamma = 0.f;
    #pragma unroll
    for (int k = 0; k < 8; k++) {
        float q = fc_b[k];
        #pragma unroll
        for (int i = 0; i < 4; i++) q = fmaf(fc_w[k*4+i], X2[i], q);
        alpha = fmaf(q, fc2_b[k],    alpha);
        beta  = fmaf(q, fc2_w[2*k],  beta);
        gamma = fmaf(q, fc2_w[2*k+1],gamma);
    }
    const float NEGL2E = -1.4426950408889634f;
    float4 abc; abc.x = alpha*NEGL2E; abc.y = beta*NEGL2E; abc.z = gamma*NEGL2E; abc.w = 0.f;
    *(float4*)&g_abc[(size_t)p*4] = abc;
    float2 xr; xr.x = xr0; xr.y = xr1;
    *(float2*)&g_xr[(size_t)p*2] = xr;
}

// ============================================================
// Kernel 3: attention partials — rank-collapsed
// per (query, part): t0 = sum s, t1 = sum s*x0, t2 = sum s*x1
// grid (5 l-tiles, 32 m-parts, 4 batches) = 640 blocks, 256 threads, 4 q/thread
// ============================================================
__global__ void __launch_bounds__(256) k_attn()
{
    __shared__ float4 sxr[MPART/2];   // 160 keys -> 80 float4 (x0a,x1a,x0b,x1b)

    const int b  = blockIdx.z;
    const int mp = blockIdx.y;
    const int lb = blockIdx.x*1024 + threadIdx.x;

    if (threadIdx.x < MPART/2)
        sxr[threadIdx.x] = ((const float4*)(g_xr + ((size_t)b*L_ + (size_t)mp*MPART)*2))[threadIdx.x];

    float al[4], be[4], ga[4];
    #pragma unroll
    for (int j = 0; j < 4; j++) {
        float4 abc = *(const float4*)&g_abc[((size_t)b*L_ + lb + j*256)*4];
        al[j] = abc.x; be[j] = abc.y; ga[j] = abc.z;
    }
    __syncthreads();

    float t0[4], t1[4], t2[4];
    #pragma unroll
    for (int j = 0; j < 4; j++) { t0[j]=0.f; t1[j]=0.f; t2[j]=0.f; }

    #pragma unroll 2
    for (int mm = 0; mm < MPART/2; mm++) {
        float4 xv = sxr[mm];   // two keys, broadcast LDS.128
        #pragma unroll
        for (int j = 0; j < 4; j++) {
            float za = fmaf(be[j], xv.x, fmaf(ga[j], xv.y, al[j]));
            float sa = frcp(1.f + fex2(za));
            t0[j] += sa;
            t1[j]  = fmaf(sa, xv.x, t1[j]);
            t2[j]  = fmaf(sa, xv.y, t2[j]);
            float zb = fmaf(be[j], xv.z, fmaf(ga[j], xv.w, al[j]));
            float sb = frcp(1.f + fex2(zb));
            t0[j] += sb;
            t1[j]  = fmaf(sb, xv.z, t1[j]);
            t2[j]  = fmaf(sb, xv.w, t2[j]);
        }
    }

    #pragma unroll
    for (int j = 0; j < 4; j++) {
        float4 w; w.x = t0[j]; w.y = t1[j]; w.z = t2[j]; w.w = 0.f;
        *(float4*)&g_part[((size_t)mp*P_ + (size_t)b*L_ + lb + j*256)*4] = w;
    }
}

// ============================================================
// Kernel 4: combine + rank-3 V reconstruct + threshold + fco -> out
// 4 threads per query, each sums 8 parts, shfl-reduce, lane sub==0 writes
// ============================================================
__global__ void __launch_bounds__(256) k_combine(
    const float* __restrict__ fc3_w, const float* __restrict__ fc3_b,
    const float* __restrict__ fco_w, const float* __restrict__ fco_b,
    float* __restrict__ out)
{
    const int idx = blockIdx.x*256 + threadIdx.x;
    const int p   = idx >> 2;
    const int sub = idx & 3;

    float t0=0.f, t1=0.f, t2=0.f;
    #pragma unroll
    for (int i = 0; i < NPART/4; i++) {
        const int s = sub*(NPART/4) + i;
        float4 a = *(const float4*)&g_part[((size_t)s*P_ + p)*4];
        t0 += a.x; t1 += a.y; t2 += a.z;
    }
    t0 += __shfl_xor_sync(0xffffffffu, t0, 1);
    t1 += __shfl_xor_sync(0xffffffffu, t1, 1);
    t2 += __shfl_xor_sync(0xffffffffu, t2, 1);
    t0 += __shfl_xor_sync(0xffffffffu, t0, 2);
    t1 += __shfl_xor_sync(0xffffffffu, t1, 2);
    t2 += __shfl_xor_sync(0xffffffffu, t2, 2);

    if (sub == 0) {
        float r0 = fco_b[0], r1 = fco_b[1];
        #pragma unroll
        for (int i = 0; i < 8; i++) {
            float o = fmaf(t0, fc3_b[i], fmaf(t1, fc3_w[2*i], t2*fc3_w[2*i+1]));
            o = (o > 0.5f) ? o : 0.f;
            r0 = fmaf(fco_w[i],   o, r0);
            r1 = fmaf(fco_w[8+i], o, r1);
        }
        const int b = p / L_;
        const int l = p % L_;
        const int t = l / N_;
        const int n = l % N_;
        out[((b*2+0)*T_ + t)*N_ + n] = r0;
        out[((b*2+1)*T_ + t)*N_ + n] = r1;
    }
}

// ============================================================
extern "C" void kernel_launch(void* const* d_in, const int* in_sizes, int n_in,
                              void* d_out, int out_size)
{
    const float* x      = (const float*)d_in[0];
    const float* md     = (const float*)d_in[1];
    const float* w_ih   = (const float*)d_in[2];
    const float* b_ih   = (const float*)d_in[3];
    const float* b_hh   = (const float*)d_in[4];
    const float* comp_w = (const float*)d_in[5];
    const float* comp_b = (const float*)d_in[6];
    const float* vf_w   = (const float*)d_in[7];
    const float* vf_b   = (const float*)d_in[8];
    const float* fc_w   = (const float*)d_in[9];
    const float* fc_b   = (const float*)d_in[10];
    const float* fc2_w  = (const float*)d_in[11];
    const float* fc2_b  = (const float*)d_in[12];
    const float* fc3_w  = (const float*)d_in[13];
    const float* fc3_b  = (const float*)d_in[14];
    const float* fco_w  = (const float*)d_in[15];
    const float* fco_b  = (const float*)d_in[16];
    float* out = (float*)d_out;

    k_compress<<<128, 256>>>(md, comp_w, comp_b, vf_w);
    k_points<<<P_/256, 256>>>(x, w_ih, b_ih, b_hh, vf_w, vf_b,
                              fc_w, fc_b, fc2_w, fc2_b);
    k_attn<<<dim3(L_/1024, NPART, B_), 256>>>();
    k_combine<<<(P_*4)/256, 256>>>(fc3_w, fc3_b, fco_w, fco_b, out);
}